// round 16
// baseline (speedup 1.0000x reference)
#include <cuda_runtime.h>
#include <cuda_bf16.h>
#include <cuda_fp16.h>
#include <cstdint>

#define NN   100000
#define EE   800000
#define DIN_ 256
#define HH   128
#define EPSF 1e-5f

#if defined(__CUDA_ARCH__) && (defined(__CUDA_ARCH_FEAT_SM103_ALL) || defined(__CUDA_ARCH_FEAT_SM100_ALL) || defined(__CUDA_ARCH_SPECIFIC__))
#define TC_OK 1
#else
#define TC_OK 0
#endif

// ---------------- static device scratch ----------------
__device__ __align__(16) __half g_t[(size_t)NN * HH];  // GEMM output fp16 (dis-scaled layers 2,3)
__device__ float g_agg[(size_t)NN * HH];               // aggregated output fp32 (pre-BN)
__device__ int   g_deg[NN];
__device__ int   g_rowptr[NN + 1];
__device__ int   g_cursor[NN];
__device__ int   g_col[EE];
__device__ float g_dis[NN];
__device__ float g_sums[3][HH];
__device__ float g_sumsqs[3][HH];
__device__ int   g_bsum[400];
// packed W: W1 bf16 hi/lo 4x32KB @0; W2 fp16 2x16KB @131072; W3 fp16 2x16KB @163840
__device__ __align__(16) unsigned char g_wpack[262144];

// GEMM1 (bf16 hi/lo) smem: {Ahi:0,Alo:16K,Bhi:32K,Blo:48K} hdr@65536
#define GSM_HDR   65536
#define GSM_TOTAL (GSM_HDR + 64)
// GEMM f16 smem: {A:0 16K, B:16384 16K} hdr@32768, bnsc@32832, bnsh@33344
#define GSMF_HDR   32768
#define GSMF_BNSC  (GSMF_HDR + 64)
#define GSMF_BNSH  (GSMF_BNSC + 512)
#define GSMF_TOTAL (GSMF_BNSH + 512)

// swizzle helper (used by both TC and fallback paths)
__device__ __forceinline__ uint32_t sw128(uint32_t o) { return o ^ ((o >> 3) & 0x70); }

#if TC_OK
// ---------------- tcgen05 ptx helpers ----------------
__device__ __forceinline__ uint32_t smem_u32(const void* p) {
    uint32_t a;
    asm("{ .reg .u64 t; cvta.to.shared.u64 t, %1; cvt.u32.u64 %0, t; }" : "=r"(a) : "l"(p));
    return a;
}
__device__ __forceinline__ uint32_t elect1() {
    uint32_t r;
    asm volatile("{ .reg .pred p; elect.sync _|p, 0xFFFFFFFF; selp.b32 %0, 1, 0, p; }" : "=r"(r));
    return r;
}
__device__ __forceinline__ void tc_alloc(uint32_t smem_addr, uint32_t n) {
    asm volatile("tcgen05.alloc.cta_group::1.sync.aligned.shared::cta.b32 [%0], %1;"
                 :: "r"(smem_addr), "r"(n) : "memory");
}
__device__ __forceinline__ void tc_relinq() {
    asm volatile("tcgen05.relinquish_alloc_permit.cta_group::1.sync.aligned;");
}
__device__ __forceinline__ void tc_dealloc(uint32_t tmem, uint32_t n) {
    asm volatile("tcgen05.dealloc.cta_group::1.sync.aligned.b32 %0, %1;" :: "r"(tmem), "r"(n));
}
__device__ __forceinline__ void tc_commit(uint32_t mbar) {
    asm volatile("tcgen05.commit.cta_group::1.mbarrier::arrive::one.shared::cluster.b64 [%0];"
                 :: "r"(mbar) : "memory");
}
__device__ __forceinline__ void mbar_init(uint32_t a, uint32_t c) {
    asm volatile("mbarrier.init.shared.b64 [%0], %1;" :: "r"(a), "r"(c) : "memory");
}
__device__ __forceinline__ void mbar_wait(uint32_t a, uint32_t ph) {
    asm volatile(
        "{\n\t.reg .pred P;\n"
        "W%=:\n\t"
        "mbarrier.try_wait.parity.acquire.cta.shared::cta.b64 P, [%0], %1, 0x989680;\n\t"
        "@P bra.uni D%=;\n\t"
        "bra.uni W%=;\n"
        "D%=:\n\t}"
        :: "r"(a), "r"(ph) : "memory");
}
__device__ __forceinline__ void tc_wait_ld()  { asm volatile("tcgen05.wait::ld.sync.aligned;" ::: "memory"); }
__device__ __forceinline__ void tc_fence_after() { asm volatile("tcgen05.fence::after_thread_sync;" ::: "memory"); }
__device__ __forceinline__ void fence_async() { asm volatile("fence.proxy.async;" ::: "memory"); }

__device__ __forceinline__ void mma_f16k(uint32_t d, uint64_t a, uint64_t b, uint32_t id, uint32_t en) {
    asm volatile(
        "{\n\t.reg .pred p;\n\tsetp.ne.u32 p, %5, 0;\n\t"
        "tcgen05.mma.cta_group::1.kind::f16 [%0], %1, %2, %3, {%4, %4, %4, %4}, p;\n\t}"
        :: "r"(d), "l"(a), "l"(b), "r"(id), "r"(0u), "r"(en) : "memory");
}
__device__ __forceinline__ void ldtm_x32(uint32_t* r, uint32_t addr) {
    asm volatile(
        "tcgen05.ld.sync.aligned.32x32b.x32.b32 "
        "{%0, %1, %2, %3, %4, %5, %6, %7, %8, %9, %10, %11, %12, %13, %14, %15, "
        "%16, %17, %18, %19, %20, %21, %22, %23, %24, %25, %26, %27, %28, %29, %30, %31}, [%32];"
        : "=r"(r[0]), "=r"(r[1]), "=r"(r[2]), "=r"(r[3]), "=r"(r[4]), "=r"(r[5]), "=r"(r[6]), "=r"(r[7]),
          "=r"(r[8]), "=r"(r[9]), "=r"(r[10]), "=r"(r[11]), "=r"(r[12]), "=r"(r[13]), "=r"(r[14]), "=r"(r[15]),
          "=r"(r[16]), "=r"(r[17]), "=r"(r[18]), "=r"(r[19]), "=r"(r[20]), "=r"(r[21]), "=r"(r[22]), "=r"(r[23]),
          "=r"(r[24]), "=r"(r[25]), "=r"(r[26]), "=r"(r[27]), "=r"(r[28]), "=r"(r[29]), "=r"(r[30]), "=r"(r[31])
        : "r"(addr));
}

__device__ __forceinline__ uint64_t smem_desc(uint32_t addr) {
    const uint64_t base = (2ull << 61) | (1ull << 46) | (64ull << 32) | (1ull << 16);
    return base | ((uint64_t)(addr >> 4) & 0x3FFF);
}
// bf16 idesc: D=f32, A=bf16(1), B=bf16(1), N=128, M=128
#define IDESC_BF16 ((1u << 4) | (1u << 7) | (1u << 10) | (16u << 17) | (8u << 24))
// fp16 idesc: D=f32, A=f16(0), B=f16(0), N=128, M=128
#define IDESC_F16  ((1u << 4) | (16u << 17) | (8u << 24))

__device__ __forceinline__ void split8(const float* v, uint32_t* hi, uint32_t* lo) {
    #pragma unroll
    for (int j = 0; j < 4; j++) {
        float a = v[2 * j], b = v[2 * j + 1];
        __nv_bfloat16 ha = __float2bfloat16_rn(a);
        __nv_bfloat16 hb = __float2bfloat16_rn(b);
        float la = a - __bfloat162float(ha);
        float lb = b - __bfloat162float(hb);
        __nv_bfloat162 hh; hh.x = ha; hh.y = hb;
        __nv_bfloat162 ll; ll.x = __float2bfloat16_rn(la); ll.y = __float2bfloat16_rn(lb);
        hi[j] = *(uint32_t*)&hh;
        lo[j] = *(uint32_t*)&ll;
    }
}
#endif  // TC_OK

// unpack uint2 (4 halfs) -> float4
__device__ __forceinline__ float4 h4_to_f4(uint2 u) {
    __half2 h0 = *(__half2*)&u.x;
    __half2 h1 = *(__half2*)&u.y;
    float2 f0 = __half22float2(h0);
    float2 f1 = __half22float2(h1);
    return make_float4(f0.x, f0.y, f1.x, f1.y);
}

// ---------------- W pre-pack: W1 only (gates gemm1, main stream) ----------------
__global__ void prep_w1(const float* __restrict__ W1) {
#if TC_OK
    int c = blockIdx.x;                       // 0..3
    int tid = threadIdx.x;
    unsigned char* out = g_wpack + (size_t)c * 32768;
    #pragma unroll
    for (int i = 0; i < 4; i++) {
        int e  = tid + 256 * i;
        int n  = e & 127;
        int kb = (e >> 7) * 8;
        float v[8];
        #pragma unroll
        for (int j = 0; j < 8; j++) v[j] = W1[(size_t)(c * 64 + kb + j) * 128 + n];
        uint32_t hi[4], lo[4];
        split8(v, hi, lo);
        uint32_t so = sw128((uint32_t)(n * 128 + kb * 2));
        *(uint4*)(out + so)         = make_uint4(hi[0], hi[1], hi[2], hi[3]);
        *(uint4*)(out + 16384 + so) = make_uint4(lo[0], lo[1], lo[2], lo[3]);
    }
#endif
}

// ---------------- W pre-pack: W2/W3 (gates gemm2 only; side stream) ----------------
__global__ void prep_w23(const float* __restrict__ W2, const float* __restrict__ W3) {
#if TC_OK
    int b = blockIdx.x;                       // 0..3
    int tid = threadIdx.x;
    const float* W;
    unsigned char* out;
    int c;
    if (b < 2) { W = W2; c = b;     out = g_wpack + 131072 + (size_t)c * 16384; }
    else       { W = W3; c = b - 2; out = g_wpack + 163840 + (size_t)(b - 2) * 16384; }
    #pragma unroll
    for (int i = 0; i < 4; i++) {
        int e  = tid + 256 * i;
        int n  = e & 127;
        int kb = (e >> 7) * 8;
        float v[8];
        #pragma unroll
        for (int j = 0; j < 8; j++) v[j] = W[(size_t)(c * 64 + kb + j) * 128 + n];
        __half2 h0 = __floats2half2_rn(v[0], v[1]);
        __half2 h1 = __floats2half2_rn(v[2], v[3]);
        __half2 h2 = __floats2half2_rn(v[4], v[5]);
        __half2 h3 = __floats2half2_rn(v[6], v[7]);
        uint32_t so = sw128((uint32_t)(n * 128 + kb * 2));
        *(uint4*)(out + so) = make_uint4(*(uint32_t*)&h0, *(uint32_t*)&h1,
                                         *(uint32_t*)&h2, *(uint32_t*)&h3);
    }
#endif
}

// ---------------- graph preprocessing ----------------
__global__ void zero_deg_kernel() {
    int i = blockIdx.x * 256 + threadIdx.x;
    if (i < NN) g_deg[i] = 0;
    if (blockIdx.x == 0 && threadIdx.x < HH) {
        #pragma unroll
        for (int l = 0; l < 3; l++) {
            g_sums[l][threadIdx.x]   = 0.f;
            g_sumsqs[l][threadIdx.x] = 0.f;
        }
    }
}

// 4 edges per thread (EE % 4 == 0)
__global__ void count_kernel(const int* __restrict__ dst) {
    int q = blockIdx.x * 256 + threadIdx.x;
    if (q < EE / 4) {
        int4 d = __ldg(&((const int4*)dst)[q]);
        atomicAdd(&g_deg[d.x], 1);
        atomicAdd(&g_deg[d.y], 1);
        atomicAdd(&g_deg[d.z], 1);
        atomicAdd(&g_deg[d.w], 1);
    }
}

__global__ void scan1_kernel() {
    __shared__ int wsum[8];
    int idx  = blockIdx.x * 256 + threadIdx.x;
    int lane = threadIdx.x & 31, wid = threadIdx.x >> 5;
    int v = (idx < NN) ? g_deg[idx] : 0;
    int x = v;
    #pragma unroll
    for (int o = 1; o < 32; o <<= 1) {
        int y = __shfl_up_sync(0xFFFFFFFFu, x, o);
        if (lane >= o) x += y;
    }
    if (lane == 31) wsum[wid] = x;
    __syncthreads();
    if (threadIdx.x == 0) {
        int csum = 0;
        #pragma unroll
        for (int w = 0; w < 8; w++) { int t = wsum[w]; wsum[w] = csum; csum += t; }
        g_bsum[blockIdx.x] = csum;
    }
    __syncthreads();
    if (idx < NN) g_rowptr[idx] = x - v + wsum[wid];
}

__global__ void scan2_kernel() {
    __shared__ int ws[16];
    int tid  = threadIdx.x;
    int lane = tid & 31, wid = tid >> 5;
    int v = (tid < 391) ? g_bsum[tid] : 0;
    int x = v;
    #pragma unroll
    for (int o = 1; o < 32; o <<= 1) {
        int y = __shfl_up_sync(0xFFFFFFFFu, x, o);
        if (lane >= o) x += y;
    }
    if (lane == 31) ws[wid] = x;
    __syncthreads();
    if (wid == 0) {
        int s = (lane < 16) ? ws[lane] : 0;
        #pragma unroll
        for (int o = 1; o < 16; o <<= 1) {
            int y = __shfl_up_sync(0xFFFFFFFFu, s, o);
            if (lane >= o) s += y;
        }
        if (lane < 16) ws[lane] = s;
    }
    __syncthreads();
    int excl = x - v + (wid ? ws[wid - 1] : 0);
    if (tid < 391) g_bsum[tid] = excl;
    if (tid == 390) g_bsum[391] = excl + v;
}

__global__ void scan3_kernel() {
    int idx = blockIdx.x * 256 + threadIdx.x;
    if (idx < NN) {
        int r = g_rowptr[idx] + g_bsum[blockIdx.x];
        g_rowptr[idx] = r;
        g_cursor[idx] = r;
        g_dis[idx]    = rsqrtf((float)(g_deg[idx] + 1));
    }
    if (idx == 0) g_rowptr[NN] = g_bsum[391];
}

// 4 edges per thread
__global__ void fill_kernel(const int* __restrict__ src, const int* __restrict__ dst) {
    int q = blockIdx.x * 256 + threadIdx.x;
    if (q < EE / 4) {
        int4 s = __ldg(&((const int4*)src)[q]);
        int4 d = __ldg(&((const int4*)dst)[q]);
        int p0 = atomicAdd(&g_cursor[d.x], 1);
        int p1 = atomicAdd(&g_cursor[d.y], 1);
        int p2 = atomicAdd(&g_cursor[d.z], 1);
        int p3 = atomicAdd(&g_cursor[d.w], 1);
        g_col[p0] = s.x;
        g_col[p1] = s.y;
        g_col[p2] = s.z;
        g_col[p3] = s.w;
    }
}

// ---------------- GEMM1: g_t = fp16(x @ W1)  (bf16 hi/lo 3xMMA, occupancy 3) -------
__global__ void __launch_bounds__(256, 3)
gemm_tc(const float* __restrict__ A, const unsigned char* __restrict__ wpack,
        const float* __restrict__ Wfull) {
    extern __shared__ char sm[];
    int tid  = threadIdx.x;
    int row0 = blockIdx.x * 128;
    constexpr int K = DIN_;

#if TC_OK
    uint32_t sb  = smem_u32(sm);
    int wid  = tid >> 5;
    int lane = tid & 31;
    constexpr int NC = K / 64;

    if (wid == 0) { tc_alloc(sb + GSM_HDR, 128); tc_relinq(); }
    if (tid == 0) mbar_init(sb + GSM_HDR + 8, 1);
    __syncthreads();
    uint32_t tmem;
    asm volatile("ld.shared.b32 %0, [%1];" : "=r"(tmem) : "r"(sb + GSM_HDR));
    uint32_t mb = sb + GSM_HDR + 8;

    auto load_chunk = [&](int c) {
        char* tile = sm;
        {
            int r = tid >> 1, h = tid & 1;
            int grow = row0 + r;
            const float* ap = A + (size_t)grow * K + c * 64 + h * 32;
            #pragma unroll
            for (int i = 0; i < 4; i++) {
                float v[8];
                if (grow < NN) {
                    float4 p0 = *(const float4*)(ap + i * 8);
                    float4 p1 = *(const float4*)(ap + i * 8 + 4);
                    v[0] = p0.x; v[1] = p0.y; v[2] = p0.z; v[3] = p0.w;
                    v[4] = p1.x; v[5] = p1.y; v[6] = p1.z; v[7] = p1.w;
                } else {
                    #pragma unroll
                    for (int j = 0; j < 8; j++) v[j] = 0.f;
                }
                uint32_t hi[4], lo[4];
                split8(v, hi, lo);
                uint32_t so = sw128((uint32_t)(r * 128 + h * 64 + i * 16));
                *(uint4*)(tile + so)         = make_uint4(hi[0], hi[1], hi[2], hi[3]);
                *(uint4*)(tile + 16384 + so) = make_uint4(lo[0], lo[1], lo[2], lo[3]);
            }
        }
        {
            const uint4* ws = (const uint4*)(wpack + (size_t)c * 32768);
            uint4* bd = (uint4*)(tile + 32768);
            #pragma unroll
            for (int i = 0; i < 8; i++) {
                int idx = tid + 256 * i;
                bd[idx] = __ldg(&ws[idx]);
            }
        }
    };

    load_chunk(0);
    fence_async();
    __syncthreads();

    uint64_t ah = smem_desc(sb);
    uint64_t al = smem_desc(sb + 16384);
    uint64_t bh = smem_desc(sb + 32768);
    uint64_t bl = smem_desc(sb + 49152);

    for (int c = 0; c < NC; c++) {
        if (wid == 0 && elect1()) {
            #pragma unroll
            for (int k = 0; k < 4; k++) {
                mma_f16k(tmem, ah + k * 2, bh + k * 2, IDESC_BF16, (c > 0) || (k > 0));
                mma_f16k(tmem, al + k * 2, bh + k * 2, IDESC_BF16, 1);
                mma_f16k(tmem, ah + k * 2, bl + k * 2, IDESC_BF16, 1);
            }
            tc_commit(mb);
        }
        if (c + 1 < NC) {
            mbar_wait(mb, (uint32_t)(c & 1));
            load_chunk(c + 1);
            fence_async();
            __syncthreads();
        }
    }
    mbar_wait(mb, (uint32_t)((NC - 1) & 1));
    tc_fence_after();

    // epilogue: fp16 output via smem (144B row stride)
    int wsub  = wid & 3;
    int chalf = (wid >> 2) * 32;
    int lr    = wsub * 32 + lane;
    #pragma unroll
    for (int p = 0; p < 2; p++) {
        uint32_t regs[32];
        ldtm_x32(regs, tmem + p * 64 + chalf);
        tc_wait_ld();
        uint32_t h[16];
        #pragma unroll
        for (int j = 0; j < 16; j++) {
            __half2 hh = __floats2half2_rn(__uint_as_float(regs[2 * j]),
                                           __uint_as_float(regs[2 * j + 1]));
            h[j] = *(uint32_t*)&hh;
        }
        #pragma unroll
        for (int j = 0; j < 4; j++)
            *(uint4*)(sm + lr * 144 + chalf * 2 + j * 16) =
                make_uint4(h[4 * j], h[4 * j + 1], h[4 * j + 2], h[4 * j + 3]);
        __syncthreads();
        #pragma unroll
        for (int i = 0; i < 4; i++) {
            int idx = tid + 256 * i;
            int r   = idx >> 3;
            int g   = idx & 7;
            int gr  = row0 + r;
            if (gr < NN)
                *(uint4*)&g_t[(size_t)gr * HH + p * 64 + g * 8] = *(uint4*)(sm + r * 144 + g * 16);
        }
        __syncthreads();
    }
    if (wid == 0) tc_dealloc(tmem, 128);

#else
    // fallback fp32 FFMA GEMM (fp16 output) reading Wfull (row-major fp32)
    float* As = (float*)sm;
    float* Bs = (float*)(sm + 8192);
    int tx = tid & 15, ty = tid >> 4;
    float acc[8][8];
    #pragma unroll
    for (int i = 0; i < 8; i++)
        #pragma unroll
        for (int j = 0; j < 8; j++) acc[i][j] = 0.f;
    for (int kk = 0; kk < K; kk += 16) {
        #pragma unroll
        for (int it = 0; it < 2; it++) {
            int idx = tid + 256 * it;
            int r  = idx >> 2;
            int k4 = idx & 3;
            int grow = row0 + r;
            float4 v = make_float4(0.f, 0.f, 0.f, 0.f);
            if (grow < NN) v = *(const float4*)&A[(size_t)grow * K + kk + k4 * 4];
            As[(k4 * 4 + 0) * 128 + r] = v.x;
            As[(k4 * 4 + 1) * 128 + r] = v.y;
            As[(k4 * 4 + 2) * 128 + r] = v.z;
            As[(k4 * 4 + 3) * 128 + r] = v.w;
        }
        #pragma unroll
        for (int it = 0; it < 2; it++) {
            int idx = tid + 256 * it;
            int kr = idx >> 5;
            int c4 = idx & 31;
            *(float4*)&Bs[kr * 128 + c4 * 4] = *(const float4*)&Wfull[(size_t)(kk + kr) * 128 + c4 * 4];
        }
        __syncthreads();
        #pragma unroll
        for (int k = 0; k < 16; k++) {
            float a[8], b[8];
            #pragma unroll
            for (int i = 0; i < 8; i++) a[i] = As[k * 128 + ty * 8 + i];
            #pragma unroll
            for (int j = 0; j < 8; j++) b[j] = Bs[k * 128 + tx * 8 + j];
            #pragma unroll
            for (int i = 0; i < 8; i++)
                #pragma unroll
                for (int j = 0; j < 8; j++) acc[i][j] = fmaf(a[i], b[j], acc[i][j]);
        }
        __syncthreads();
    }
    #pragma unroll
    for (int i = 0; i < 8; i++) {
        int row = row0 + ty * 8 + i;
        if (row < NN) {
            __half2 h0 = __floats2half2_rn(acc[i][0], acc[i][1]);
            __half2 h1 = __floats2half2_rn(acc[i][2], acc[i][3]);
            __half2 h2 = __floats2half2_rn(acc[i][4], acc[i][5]);
            __half2 h3 = __floats2half2_rn(acc[i][6], acc[i][7]);
            *(uint4*)&g_t[(size_t)row * HH + tx * 8] =
                make_uint4(*(uint32_t*)&h0, *(uint32_t*)&h1, *(uint32_t*)&h2, *(uint32_t*)&h3);
        }
    }
#endif
}

// ---------------- GEMM f16 (layers 2,3): g_t = fp16(dis * (relu(bn(agg)) @ W)) ----
__global__ void __launch_bounds__(256, 4)
gemm_f16(const unsigned char* __restrict__ wpack, const float* __restrict__ Wfull,
         const float* __restrict__ gamma, const float* __restrict__ beta,
         const float* __restrict__ bsum, const float* __restrict__ bsumsq) {
    extern __shared__ char sm[];
    const float* A = (const float*)g_agg;
    int tid  = threadIdx.x;
    int row0 = blockIdx.x * 128;

#if TC_OK
    uint32_t sb  = smem_u32(sm);
    int wid  = tid >> 5;
    int lane = tid & 31;
    float* bnsc = (float*)(sm + GSMF_BNSC);
    float* bnsh = (float*)(sm + GSMF_BNSH);

    if (tid == 0) mbar_init(sb + GSMF_HDR + 8, 1);
    if (tid < 128) {
        float mu  = bsum[tid] * (1.0f / (float)NN);
        float var = bsumsq[tid] * (1.0f / (float)NN) - mu * mu;
        float sc  = gamma[tid] * rsqrtf(var + EPSF);
        bnsc[tid] = sc;
        bnsh[tid] = beta[tid] - mu * sc;
    }
    __syncthreads();

    auto load_chunk = [&](int c) {
        {
            int r = tid >> 1, h = tid & 1;
            int grow = row0 + r;
            const float* ap = A + (size_t)grow * HH + c * 64 + h * 32;
            #pragma unroll
            for (int i = 0; i < 4; i++) {
                float v[8];
                if (grow < NN) {
                    float4 p0 = *(const float4*)(ap + i * 8);
                    float4 p1 = *(const float4*)(ap + i * 8 + 4);
                    v[0] = p0.x; v[1] = p0.y; v[2] = p0.z; v[3] = p0.w;
                    v[4] = p1.x; v[5] = p1.y; v[6] = p1.z; v[7] = p1.w;
                } else {
                    #pragma unroll
                    for (int j = 0; j < 8; j++) v[j] = 0.f;
                }
                int col = c * 64 + h * 32 + i * 8;
                #pragma unroll
                for (int j = 0; j < 8; j++)
                    v[j] = fmaxf(0.f, fmaf(v[j], bnsc[col + j], bnsh[col + j]));
                __half2 h0 = __floats2half2_rn(v[0], v[1]);
                __half2 h1 = __floats2half2_rn(v[2], v[3]);
                __half2 h2 = __floats2half2_rn(v[4], v[5]);
                __half2 h3 = __floats2half2_rn(v[6], v[7]);
                uint32_t so = sw128((uint32_t)(r * 128 + h * 64 + i * 16));
                *(uint4*)(sm + so) = make_uint4(*(uint32_t*)&h0, *(uint32_t*)&h1,
                                                *(uint32_t*)&h2, *(uint32_t*)&h3);
            }
        }
        {
            const uint4* ws = (const uint4*)(wpack + (size_t)c * 16384);
            uint4* bd = (uint4*)(sm + 16384);
            #pragma unroll
            for (int i = 0; i < 4; i++) {
                int idx = tid + 256 * i;
                bd[idx] = __ldg(&ws[idx]);
            }
        }
    };

    load_chunk(0);
    fence_async();
    __syncthreads();
    if (wid == 0) { tc_alloc(sb + GSMF_HDR, 128); tc_relinq(); }
    __syncthreads();
    uint32_t tmem;
    asm volatile("ld.shared.b32 %0, [%1];" : "=r"(tmem) : "r"(sb + GSMF_HDR));
    uint32_t mb = sb + GSMF_HDR + 8;

    uint64_t ad = smem_desc(sb);
    uint64_t bd = smem_desc(sb + 16384);

    #pragma unroll
    for (int c = 0; c < 2; c++) {
        if (wid == 0 && elect1()) {
            #pragma unroll
            for (int k = 0; k < 4; k++)
                mma_f16k(tmem, ad + k * 2, bd + k * 2, IDESC_F16, (c > 0) || (k > 0));
            tc_commit(mb);
        }
        if (c == 0) {
            mbar_wait(mb, 0u);
            load_chunk(1);
            fence_async();
            __syncthreads();
        }
    }
    mbar_wait(mb, 1u);
    tc_fence_after();

    // epilogue: dis-scale, fp16 to smem (144B rows), coalesced STG
    int wsub  = wid & 3;
    int chalf = (wid >> 2) * 32;
    int lr    = wsub * 32 + lane;
    int growE = row0 + lr;
    float dv  = (growE < NN) ? g_dis[growE] : 0.f;
    #pragma unroll
    for (int p = 0; p < 2; p++) {
        uint32_t regs[32];
        ldtm_x32(regs, tmem + p * 64 + chalf);
        tc_wait_ld();
        uint32_t h[16];
        #pragma unroll
        for (int j = 0; j < 16; j++) {
            __half2 hh = __floats2half2_rn(dv * __uint_as_float(regs[2 * j]),
                                           dv * __uint_as_float(regs[2 * j + 1]));
            h[j] = *(uint32_t*)&hh;
        }
        #pragma unroll
        for (int j = 0; j < 4; j++)
            *(uint4*)(sm + lr * 144 + chalf * 2 + j * 16) =
                make_uint4(h[4 * j], h[4 * j + 1], h[4 * j + 2], h[4 * j + 3]);
        __syncthreads();
        #pragma unroll
        for (int i = 0; i < 4; i++) {
            int idx = tid + 256 * i;
            int r   = idx >> 3;
            int g   = idx & 7;
            int gr  = row0 + r;
            if (gr < NN)
                *(uint4*)&g_t[(size_t)gr * HH + p * 64 + g * 8] = *(uint4*)(sm + r * 144 + g * 16);
        }
        __syncthreads();
    }
    if (wid == 0) tc_dealloc(tmem, 128);

#else
    // fallback fp32 FFMA GEMM with BN (fp16 output) reading Wfull (row-major fp32)
    float* As = (float*)sm;
    float* Bs = (float*)(sm + 8192);
    float* bnsc = (float*)(sm + GSMF_BNSC);
    float* bnsh = (float*)(sm + GSMF_BNSH);
    if (tid < 128) {
        float mu  = bsum[tid] * (1.0f / (float)NN);
        float var = bsumsq[tid] * (1.0f / (float)NN) - mu * mu;
        float sc  = gamma[tid] * rsqrtf(var + EPSF);
        bnsc[tid] = sc;
        bnsh[tid] = beta[tid] - mu * sc;
    }
    __syncthreads();
    int tx = tid & 15, ty = tid >> 4;
    float acc[8][8];
    #pragma unroll
    for (int i = 0; i < 8; i++)
        #pragma unroll
        for (int j = 0; j < 8; j++) acc[i][j] = 0.f;
    for (int kk = 0; kk < HH; kk += 16) {
        #pragma unroll
        for (int it = 0; it < 2; it++) {
            int idx = tid + 256 * it;
            int r  = idx >> 2;
            int k4 = idx & 3;
            int grow = row0 + r;
            float4 v = make_float4(0.f, 0.f, 0.f, 0.f);
            if (grow < NN) v = *(const float4*)&A[(size_t)grow * HH + kk + k4 * 4];
            int c = kk + k4 * 4;
            v.x = fmaxf(0.f, fmaf(v.x, bnsc[c + 0], bnsh[c + 0]));
            v.y = fmaxf(0.f, fmaf(v.y, bnsc[c + 1], bnsh[c + 1]));
            v.z = fmaxf(0.f, fmaf(v.z, bnsc[c + 2], bnsh[c + 2]));
            v.w = fmaxf(0.f, fmaf(v.w, bnsc[c + 3], bnsh[c + 3]));
            As[(k4 * 4 + 0) * 128 + r] = v.x;
            As[(k4 * 4 + 1) * 128 + r] = v.y;
            As[(k4 * 4 + 2) * 128 + r] = v.z;
            As[(k4 * 4 + 3) * 128 + r] = v.w;
        }
        #pragma unroll
        for (int it = 0; it < 2; it++) {
            int idx = tid + 256 * it;
            int kr = idx >> 5;
            int c4 = idx & 31;
            *(float4*)&Bs[kr * 128 + c4 * 4] = *(const float4*)&Wfull[(size_t)(kk + kr) * 128 + c4 * 4];
        }
        __syncthreads();
        #pragma unroll
        for (int k = 0; k < 16; k++) {
            float a[8], b[8];
            #pragma unroll
            for (int i = 0; i < 8; i++) a[i] = As[k * 128 + ty * 8 + i];
            #pragma unroll
            for (int j = 0; j < 8; j++) b[j] = Bs[k * 128 + tx * 8 + j];
            #pragma unroll
            for (int i = 0; i < 8; i++)
                #pragma unroll
                for (int j = 0; j < 8; j++) acc[i][j] = fmaf(a[i], b[j], acc[i][j]);
        }
        __syncthreads();
    }
    #pragma unroll
    for (int i = 0; i < 8; i++) {
        int row = row0 + ty * 8 + i;
        if (row < NN) {
            float dv = g_dis[row];
            __half2 h0 = __floats2half2_rn(dv * acc[i][0], dv * acc[i][1]);
            __half2 h1 = __floats2half2_rn(dv * acc[i][2], dv * acc[i][3]);
            __half2 h2 = __floats2half2_rn(dv * acc[i][4], dv * acc[i][5]);
            __half2 h3 = __floats2half2_rn(dv * acc[i][6], dv * acc[i][7]);
            *(uint4*)&g_t[(size_t)row * HH + tx * 8] =
                make_uint4(*(uint32_t*)&h0, *(uint32_t*)&h1, *(uint32_t*)&h2, *(uint32_t*)&h3);
        }
    }
#endif
}

// ---------------- aggregation + fused BN stats (R11-exact: half-warp/node, 2-deep) ----
#define AGG_BLOCKS 1184
template <bool EDGE_DIS>
__global__ void __launch_bounds__(256) agg_kernel(const float* __restrict__ bias,
                                                  float* __restrict__ bsum,
                                                  float* __restrict__ bsumsq) {
    __shared__ float spart[16][128];
    int hw = threadIdx.x >> 4;       // half-warp id 0..15
    int hl = threadIdx.x & 15;       // lane within half-warp
    int node0 = blockIdx.x * 16 + hw;
    const int stride = AGG_BLOCKS * 16;
    const uint4* t4 = (const uint4*)g_t;     // 16 uint4 per 128-half row
    float4 bb0 = ((const float4*)bias)[hl * 2];
    float4 bb1 = ((const float4*)bias)[hl * 2 + 1];

    float ps[8], pq[8];
    #pragma unroll
    for (int j = 0; j < 8; j++) { ps[j] = 0.f; pq[j] = 0.f; }

    for (int v = node0; v < NN; v += stride) {
        int beg = g_rowptr[v], end = g_rowptr[v + 1];
        float a0[8], a1[8];
        #pragma unroll
        for (int j = 0; j < 8; j++) { a0[j] = 0.f; a1[j] = 0.f; }
        int e  = beg;
        int sA = (e     < end) ? __ldg(&g_col[e])     : 0;
        int sB = (e + 1 < end) ? __ldg(&g_col[e + 1]) : 0;
        while (e + 2 <= end) {
            int sa = sA, sb = sB;
            sA = (e + 2 < end) ? __ldg(&g_col[e + 2]) : 0;
            sB = (e + 3 < end) ? __ldg(&g_col[e + 3]) : 0;
            uint4 ua = __ldg(&t4[(size_t)sa * 16 + hl]);
            uint4 ub = __ldg(&t4[(size_t)sb * 16 + hl]);
            float4 ta0 = h4_to_f4(make_uint2(ua.x, ua.y));
            float4 ta1 = h4_to_f4(make_uint2(ua.z, ua.w));
            float4 tb0 = h4_to_f4(make_uint2(ub.x, ub.y));
            float4 tb1 = h4_to_f4(make_uint2(ub.z, ub.w));
            if (EDGE_DIS) {
                float wa = __ldg(&g_dis[sa]);
                float wb = __ldg(&g_dis[sb]);
                a0[0] = fmaf(wa, ta0.x, a0[0]); a0[1] = fmaf(wa, ta0.y, a0[1]);
                a0[2] = fmaf(wa, ta0.z, a0[2]); a0[3] = fmaf(wa, ta0.w, a0[3]);
                a0[4] = fmaf(wa, ta1.x, a0[4]); a0[5] = fmaf(wa, ta1.y, a0[5]);
                a0[6] = fmaf(wa, ta1.z, a0[6]); a0[7] = fmaf(wa, ta1.w, a0[7]);
                a1[0] = fmaf(wb, tb0.x, a1[0]); a1[1] = fmaf(wb, tb0.y, a1[1]);
                a1[2] = fmaf(wb, tb0.z, a1[2]); a1[3] = fmaf(wb, tb0.w, a1[3]);
                a1[4] = fmaf(wb, tb1.x, a1[4]); a1[5] = fmaf(wb, tb1.y, a1[5]);
                a1[6] = fmaf(wb, tb1.z, a1[6]); a1[7] = fmaf(wb, tb1.w, a1[7]);
            } else {
                a0[0] += ta0.x; a0[1] += ta0.y; a0[2] += ta0.z; a0[3] += ta0.w;
                a0[4] += ta1.x; a0[5] += ta1.y; a0[6] += ta1.z; a0[7] += ta1.w;
                a1[0] += tb0.x; a1[1] += tb0.y; a1[2] += tb0.z; a1[3] += tb0.w;
                a1[4] += tb1.x; a1[5] += tb1.y; a1[6] += tb1.z; a1[7] += tb1.w;
            }
            e += 2;
        }
        if (e < end) {
            uint4 ua = __ldg(&t4[(size_t)sA * 16 + hl]);
            float4 ta0 = h4_to_f4(make_uint2(ua.x, ua.y));
            float4 ta1 = h4_to_f4(make_uint2(ua.z, ua.w));
            if (EDGE_DIS) {
                float wa = __ldg(&g_dis[sA]);
                a0[0] = fmaf(wa, ta0.x, a0[0]); a0[1] = fmaf(wa, ta0.y, a0[1]);
                a0[2] = fmaf(wa, ta0.z, a0[2]); a0[3] = fmaf(wa, ta0.w, a0[3]);
                a0[4] = fmaf(wa, ta1.x, a0[4]); a0[5] = fmaf(wa, ta1.y, a0[5]);
                a0[6] = fmaf(wa, ta1.z, a0[6]); a0[7] = fmaf(wa, ta1.w, a0[7]);
            } else {
                a0[0] += ta0.x; a0[1] += ta0.y; a0[2] += ta0.z; a0[3] += ta0.w;
                a0[4] += ta1.x; a0[5] += ta1.y; a0[6] += ta1.z; a0[7] += ta1.w;
            }
        }
        float dv = g_dis[v];
        uint4 us = t4[(size_t)v * 16 + hl];
        float4 sv0 = h4_to_f4(make_uint2(us.x, us.y));
        float4 sv1 = h4_to_f4(make_uint2(us.z, us.w));
        float svv[8] = { sv0.x, sv0.y, sv0.z, sv0.w, sv1.x, sv1.y, sv1.z, sv1.w };
        float bbv[8] = { bb0.x, bb0.y, bb0.z, bb0.w, bb1.x, bb1.y, bb1.z, bb1.w };
        float o[8];
        #pragma unroll
        for (int j = 0; j < 8; j++) {
            if (EDGE_DIS)
                o[j] = fmaf(dv, fmaf(dv, svv[j], a0[j] + a1[j]), bbv[j]);
            else
                o[j] = fmaf(dv, a0[j] + a1[j] + svv[j], bbv[j]);
        }
        float* op = &g_agg[(size_t)v * HH + hl * 8];
        *(float4*)(op)     = make_float4(o[0], o[1], o[2], o[3]);
        *(float4*)(op + 4) = make_float4(o[4], o[5], o[6], o[7]);
        #pragma unroll
        for (int j = 0; j < 8; j++) {
            ps[j] += o[j];
            pq[j]  = fmaf(o[j], o[j], pq[j]);
        }
    }

    // block reduce: 16 half-warps x 128 cols
    *(float4*)&spart[hw][hl * 8]     = make_float4(ps[0], ps[1], ps[2], ps[3]);
    *(float4*)&spart[hw][hl * 8 + 4] = make_float4(ps[4], ps[5], ps[6], ps[7]);
    __syncthreads();
    if (threadIdx.x < 128) {
        float s = 0.f;
        #pragma unroll
        for (int w = 0; w < 16; w++) s += spart[w][threadIdx.x];
        atomicAdd(&bsum[threadIdx.x], s);
    }
    __syncthreads();
    *(float4*)&spart[hw][hl * 8]     = make_float4(pq[0], pq[1], pq[2], pq[3]);
    *(float4*)&spart[hw][hl * 8 + 4] = make_float4(pq[4], pq[5], pq[6], pq[7]);
    __syncthreads();
    if (threadIdx.x < 128) {
        float s = 0.f;
        #pragma unroll
        for (int w = 0; w < 16; w++) s += spart[w][threadIdx.x];
        atomicAdd(&bsumsq[threadIdx.x], s);
    }
}

// ---------------- final projection (BN3 inline, grid-stride, coeffs hoisted) ----------
#define FIN_BLOCKS 1184
__global__ void __launch_bounds__(256) final_kernel(const float* __restrict__ Wf,
                                                    const float* __restrict__ bf,
                                                    const float* __restrict__ gamma,
                                                    const float* __restrict__ beta,
                                                    float* __restrict__ out) {
    int wid  = threadIdx.x >> 5;
    int lane = threadIdx.x & 31;
    float4 S  = ((const float4*)g_sums[2])[lane];
    float4 Q  = ((const float4*)g_sumsqs[2])[lane];
    float4 gm = ((const float4*)gamma)[lane];
    float4 be = ((const float4*)beta)[lane];
    const float inv = 1.0f / (float)NN;
    float mux = S.x * inv, muy = S.y * inv, muz = S.z * inv, muw = S.w * inv;
    float scx = gm.x * rsqrtf(Q.x * inv - mux * mux + EPSF);
    float scy = gm.y * rsqrtf(Q.y * inv - muy * muy + EPSF);
    float scz = gm.z * rsqrtf(Q.z * inv - muz * muz + EPSF);
    float scw = gm.w * rsqrtf(Q.w * inv - muw * muw + EPSF);
    float shx = be.x - mux * scx, shy = be.y - muy * scy;
    float shz = be.z - muz * scz, shw = be.w - muw * scw;
    float4 w  = ((const float4*)Wf)[lane];
    float bf0 = bf[0];

    for (int v = blockIdx.x * 8 + wid; v < NN; v += FIN_BLOCKS * 8) {
        float4 h = ((const float4*)g_agg)[(size_t)v * 32 + lane];
        float r = fmaxf(0.f, fmaf(h.x, scx, shx)) * w.x
                + fmaxf(0.f, fmaf(h.y, scy, shy)) * w.y
                + fmaxf(0.f, fmaf(h.z, scz, shz)) * w.z
                + fmaxf(0.f, fmaf(h.w, scw, shw)) * w.w;
        #pragma unroll
        for (int o = 16; o; o >>= 1) r += __shfl_down_sync(0xFFFFFFFFu, r, o);
        if (lane == 0) out[v] = r + bf0;
    }
}

// ---------------- launch ----------------
extern "C" void kernel_launch(void* const* d_in, const int* in_sizes, int n_in,
                              void* d_out, int out_size) {
    const float* x   = (const float*)d_in[0];
    const int*   src = (const int*)d_in[1];
    const int*   dst = (const int*)d_in[2];
    const float* W1  = (const float*)d_in[3];
    const float* b1  = (const float*)d_in[4];
    const float* g1  = (const float*)d_in[5];
    const float* be1 = (const float*)d_in[6];
    const float* W2  = (const float*)d_in[7];
    const float* b2  = (const float*)d_in[8];
    const float* g2  = (const float*)d_in[9];
    const float* be2 = (const float*)d_in[10];
    const float* W3  = (const float*)d_in[11];
    const float* b3  = (const float*)d_in[12];
    const float* g3  = (const float*)d_in[13];
    const float* be3 = (const float*)d_in[14];
    const float* Wf  = (const float*)d_in[15];
    const float* bf  = (const float*)d_in[16];
    float* out = (float*)d_out;

    cudaFuncSetAttribute(gemm_tc,  cudaFuncAttributeMaxDynamicSharedMemorySize, GSM_TOTAL);
    cudaFuncSetAttribute(gemm_f16, cudaFuncAttributeMaxDynamicSharedMemorySize, GSMF_TOTAL);

    unsigned char* wp;
    cudaGetSymbolAddress((void**)&wp, g_wpack);
    float *sums, *sumsqs;
    cudaGetSymbolAddress((void**)&sums,   g_sums);
    cudaGetSymbolAddress((void**)&sumsqs, g_sumsqs);

    const int E4B = (EE / 4 + 255) / 256;          // 782 (4 edges/thread)
    const int NB  = (NN + 255) / 256;              // 391
    const int GB  = (NN + 127) / 128;              // 782

    static cudaStream_t s2 = nullptr;
    static cudaEvent_t evFork = nullptr, evJoin = nullptr;
    static int stream_ok = -1;
    if (stream_ok < 0) {
        stream_ok = (cudaStreamCreateWithFlags(&s2, cudaStreamNonBlocking) == cudaSuccess &&
                     cudaEventCreateWithFlags(&evFork, cudaEventDisableTiming) == cudaSuccess &&
                     cudaEventCreateWithFlags(&evJoin, cudaEventDisableTiming) == cudaSuccess) ? 1 : 0;
    }

    if (stream_ok == 1) {
        cudaEventRecord(evFork, 0);
        cudaStreamWaitEvent(s2, evFork, 0);
        zero_deg_kernel<<<NB, 256, 0, s2>>>();
        count_kernel<<<E4B, 256, 0, s2>>>(dst);
        scan1_kernel<<<NB, 256, 0, s2>>>();
        scan2_kernel<<<1, 512, 0, s2>>>();
        scan3_kernel<<<NB, 256, 0, s2>>>();
        fill_kernel<<<E4B, 256, 0, s2>>>(src, dst);
        prep_w23<<<4, 256, 0, s2>>>(W2, W3);       // only gates gemm2 (after join)
        cudaEventRecord(evJoin, s2);

        prep_w1<<<4, 256>>>(W1);
        gemm_tc<<<GB, 256, GSM_TOTAL>>>(x, wp, W1);
        cudaStreamWaitEvent(0, evJoin, 0);
    } else {
        zero_deg_kernel<<<NB, 256>>>();
        count_kernel<<<E4B, 256>>>(dst);
        scan1_kernel<<<NB, 256>>>();
        scan2_kernel<<<1, 512>>>();
        scan3_kernel<<<NB, 256>>>();
        fill_kernel<<<E4B, 256>>>(src, dst);
        prep_w23<<<4, 256>>>(W2, W3);
        prep_w1<<<4, 256>>>(W1);
        gemm_tc<<<GB, 256, GSM_TOTAL>>>(x, wp, W1);
    }

    // layer 1: t unscaled -> per-edge dis agg
    agg_kernel<true><<<AGG_BLOCKS, 256>>>(b1, sums + 0 * HH, sumsqs + 0 * HH);

    // layer 2: fp16 single-MMA GEMM (BN from sums[0]); epilogue pre-scales by dis
    gemm_f16<<<GB, 256, GSMF_TOTAL>>>(wp + 131072, W2, g1, be1, sums + 0 * HH, sumsqs + 0 * HH);
    agg_kernel<false><<<AGG_BLOCKS, 256>>>(b2, sums + 1 * HH, sumsqs + 1 * HH);

    // layer 3
    gemm_f16<<<GB, 256, GSMF_TOTAL>>>(wp + 163840, W3, g2, be2, sums + 1 * HH, sumsqs + 1 * HH);
    agg_kernel<false><<<AGG_BLOCKS, 256>>>(b3, sums + 2 * HH, sumsqs + 2 * HH);

    // final projection (BN3 inline, grid-stride)
    final_kernel<<<FIN_BLOCKS, 256>>>(Wf, bf, g3, be3, out);
}

// round 17
// speedup vs baseline: 1.0315x; 1.0315x over previous
#include <cuda_runtime.h>
#include <cuda_bf16.h>
#include <cuda_fp16.h>
#include <cstdint>

#define NN   100000
#define EE   800000
#define DIN_ 256
#define HH   128
#define EPSF 1e-5f

#if defined(__CUDA_ARCH__) && (defined(__CUDA_ARCH_FEAT_SM103_ALL) || defined(__CUDA_ARCH_FEAT_SM100_ALL) || defined(__CUDA_ARCH_SPECIFIC__))
#define TC_OK 1
#else
#define TC_OK 0
#endif

// ---------------- static device scratch ----------------
__device__ __align__(16) __half g_t[(size_t)NN * HH];  // GEMM output fp16 (dis-scaled layers 2,3)
__device__ float g_agg[(size_t)NN * HH];               // aggregated output fp32 (pre-BN)
__device__ int   g_deg[NN];
__device__ int   g_rowptr[NN + 1];
__device__ int   g_cursor[NN];
__device__ int   g_col[EE];
__device__ float g_dis[NN];
__device__ float g_sums[3][HH];
__device__ float g_sumsqs[3][HH];
__device__ int   g_bsum[400];
// packed W: W1 bf16 hi/lo 4x32KB @0; W2 fp16 2x16KB @131072; W3 fp16 2x16KB @163840
__device__ __align__(16) unsigned char g_wpack[262144];

// GEMM1 (bf16 hi/lo) smem: {Ahi:0,Alo:16K,Bhi:32K,Blo:48K} hdr@65536
#define GSM_HDR   65536
#define GSM_TOTAL (GSM_HDR + 64)
// GEMM f16 smem: {A:0 16K, B:16384 16K} hdr@32768, bnsc@32832, bnsh@33344
#define GSMF_HDR   32768
#define GSMF_BNSC  (GSMF_HDR + 64)
#define GSMF_BNSH  (GSMF_BNSC + 512)
#define GSMF_TOTAL (GSMF_BNSH + 512)

// swizzle helper (used by both TC and fallback paths)
__device__ __forceinline__ uint32_t sw128(uint32_t o) { return o ^ ((o >> 3) & 0x70); }

#if TC_OK
// ---------------- tcgen05 ptx helpers ----------------
__device__ __forceinline__ uint32_t smem_u32(const void* p) {
    uint32_t a;
    asm("{ .reg .u64 t; cvta.to.shared.u64 t, %1; cvt.u32.u64 %0, t; }" : "=r"(a) : "l"(p));
    return a;
}
__device__ __forceinline__ uint32_t elect1() {
    uint32_t r;
    asm volatile("{ .reg .pred p; elect.sync _|p, 0xFFFFFFFF; selp.b32 %0, 1, 0, p; }" : "=r"(r));
    return r;
}
__device__ __forceinline__ void tc_alloc(uint32_t smem_addr, uint32_t n) {
    asm volatile("tcgen05.alloc.cta_group::1.sync.aligned.shared::cta.b32 [%0], %1;"
                 :: "r"(smem_addr), "r"(n) : "memory");
}
__device__ __forceinline__ void tc_relinq() {
    asm volatile("tcgen05.relinquish_alloc_permit.cta_group::1.sync.aligned;");
}
__device__ __forceinline__ void tc_dealloc(uint32_t tmem, uint32_t n) {
    asm volatile("tcgen05.dealloc.cta_group::1.sync.aligned.b32 %0, %1;" :: "r"(tmem), "r"(n));
}
__device__ __forceinline__ void tc_commit(uint32_t mbar) {
    asm volatile("tcgen05.commit.cta_group::1.mbarrier::arrive::one.shared::cluster.b64 [%0];"
                 :: "r"(mbar) : "memory");
}
__device__ __forceinline__ void mbar_init(uint32_t a, uint32_t c) {
    asm volatile("mbarrier.init.shared.b64 [%0], %1;" :: "r"(a), "r"(c) : "memory");
}
__device__ __forceinline__ void mbar_wait(uint32_t a, uint32_t ph) {
    asm volatile(
        "{\n\t.reg .pred P;\n"
        "W%=:\n\t"
        "mbarrier.try_wait.parity.acquire.cta.shared::cta.b64 P, [%0], %1, 0x989680;\n\t"
        "@P bra.uni D%=;\n\t"
        "bra.uni W%=;\n"
        "D%=:\n\t}"
        :: "r"(a), "r"(ph) : "memory");
}
__device__ __forceinline__ void tc_wait_ld()  { asm volatile("tcgen05.wait::ld.sync.aligned;" ::: "memory"); }
__device__ __forceinline__ void tc_fence_after() { asm volatile("tcgen05.fence::after_thread_sync;" ::: "memory"); }
__device__ __forceinline__ void fence_async() { asm volatile("fence.proxy.async;" ::: "memory"); }

__device__ __forceinline__ void mma_f16k(uint32_t d, uint64_t a, uint64_t b, uint32_t id, uint32_t en) {
    asm volatile(
        "{\n\t.reg .pred p;\n\tsetp.ne.u32 p, %5, 0;\n\t"
        "tcgen05.mma.cta_group::1.kind::f16 [%0], %1, %2, %3, {%4, %4, %4, %4}, p;\n\t}"
        :: "r"(d), "l"(a), "l"(b), "r"(id), "r"(0u), "r"(en) : "memory");
}
__device__ __forceinline__ void ldtm_x32(uint32_t* r, uint32_t addr) {
    asm volatile(
        "tcgen05.ld.sync.aligned.32x32b.x32.b32 "
        "{%0, %1, %2, %3, %4, %5, %6, %7, %8, %9, %10, %11, %12, %13, %14, %15, "
        "%16, %17, %18, %19, %20, %21, %22, %23, %24, %25, %26, %27, %28, %29, %30, %31}, [%32];"
        : "=r"(r[0]), "=r"(r[1]), "=r"(r[2]), "=r"(r[3]), "=r"(r[4]), "=r"(r[5]), "=r"(r[6]), "=r"(r[7]),
          "=r"(r[8]), "=r"(r[9]), "=r"(r[10]), "=r"(r[11]), "=r"(r[12]), "=r"(r[13]), "=r"(r[14]), "=r"(r[15]),
          "=r"(r[16]), "=r"(r[17]), "=r"(r[18]), "=r"(r[19]), "=r"(r[20]), "=r"(r[21]), "=r"(r[22]), "=r"(r[23]),
          "=r"(r[24]), "=r"(r[25]), "=r"(r[26]), "=r"(r[27]), "=r"(r[28]), "=r"(r[29]), "=r"(r[30]), "=r"(r[31])
        : "r"(addr));
}

__device__ __forceinline__ uint64_t smem_desc(uint32_t addr) {
    const uint64_t base = (2ull << 61) | (1ull << 46) | (64ull << 32) | (1ull << 16);
    return base | ((uint64_t)(addr >> 4) & 0x3FFF);
}
// bf16 idesc: D=f32, A=bf16(1), B=bf16(1), N=128, M=128
#define IDESC_BF16 ((1u << 4) | (1u << 7) | (1u << 10) | (16u << 17) | (8u << 24))
// fp16 idesc: D=f32, A=f16(0), B=f16(0), N=128, M=128
#define IDESC_F16  ((1u << 4) | (16u << 17) | (8u << 24))

__device__ __forceinline__ void split8(const float* v, uint32_t* hi, uint32_t* lo) {
    #pragma unroll
    for (int j = 0; j < 4; j++) {
        float a = v[2 * j], b = v[2 * j + 1];
        __nv_bfloat16 ha = __float2bfloat16_rn(a);
        __nv_bfloat16 hb = __float2bfloat16_rn(b);
        float la = a - __bfloat162float(ha);
        float lb = b - __bfloat162float(hb);
        __nv_bfloat162 hh; hh.x = ha; hh.y = hb;
        __nv_bfloat162 ll; ll.x = __float2bfloat16_rn(la); ll.y = __float2bfloat16_rn(lb);
        hi[j] = *(uint32_t*)&hh;
        lo[j] = *(uint32_t*)&ll;
    }
}
#endif  // TC_OK

// unpack uint2 (4 halfs) -> float4
__device__ __forceinline__ float4 h4_to_f4(uint2 u) {
    __half2 h0 = *(__half2*)&u.x;
    __half2 h1 = *(__half2*)&u.y;
    float2 f0 = __half22float2(h0);
    float2 f1 = __half22float2(h1);
    return make_float4(f0.x, f0.y, f1.x, f1.y);
}

// ---------------- W pre-pack ----------------
__global__ void prep_w(const float* __restrict__ W1, const float* __restrict__ W2,
                       const float* __restrict__ W3) {
#if TC_OK
    int b = blockIdx.x;
    int tid = threadIdx.x;
    if (b < 4) {
        const float* W = W1;
        int c = b;
        unsigned char* out = g_wpack + (size_t)b * 32768;
        #pragma unroll
        for (int i = 0; i < 4; i++) {
            int e  = tid + 256 * i;
            int n  = e & 127;
            int kb = (e >> 7) * 8;
            float v[8];
            #pragma unroll
            for (int j = 0; j < 8; j++) v[j] = W[(size_t)(c * 64 + kb + j) * 128 + n];
            uint32_t hi[4], lo[4];
            split8(v, hi, lo);
            uint32_t so = sw128((uint32_t)(n * 128 + kb * 2));
            *(uint4*)(out + so)         = make_uint4(hi[0], hi[1], hi[2], hi[3]);
            *(uint4*)(out + 16384 + so) = make_uint4(lo[0], lo[1], lo[2], lo[3]);
        }
    } else {
        const float* W;
        unsigned char* out;
        int c;
        if (b < 6) { W = W2; c = b - 4; out = g_wpack + 131072 + (size_t)c * 16384; }
        else       { W = W3; c = b - 6; out = g_wpack + 163840 + (size_t)(b - 6) * 16384; }
        #pragma unroll
        for (int i = 0; i < 4; i++) {
            int e  = tid + 256 * i;
            int n  = e & 127;
            int kb = (e >> 7) * 8;
            float v[8];
            #pragma unroll
            for (int j = 0; j < 8; j++) v[j] = W[(size_t)(c * 64 + kb + j) * 128 + n];
            __half2 h0 = __floats2half2_rn(v[0], v[1]);
            __half2 h1 = __floats2half2_rn(v[2], v[3]);
            __half2 h2 = __floats2half2_rn(v[4], v[5]);
            __half2 h3 = __floats2half2_rn(v[6], v[7]);
            uint32_t so = sw128((uint32_t)(n * 128 + kb * 2));
            *(uint4*)(out + so) = make_uint4(*(uint32_t*)&h0, *(uint32_t*)&h1,
                                             *(uint32_t*)&h2, *(uint32_t*)&h3);
        }
    }
#endif
}

// ---------------- graph preprocessing ----------------
__global__ void zero_deg_kernel() {
    int i = blockIdx.x * 256 + threadIdx.x;
    if (i < NN) g_deg[i] = 0;
    if (blockIdx.x == 0 && threadIdx.x < HH) {
        #pragma unroll
        for (int l = 0; l < 3; l++) {
            g_sums[l][threadIdx.x]   = 0.f;
            g_sumsqs[l][threadIdx.x] = 0.f;
        }
    }
}

__global__ void count_kernel(const int* __restrict__ dst) {
    int e = blockIdx.x * 256 + threadIdx.x;
    if (e < EE) atomicAdd(&g_deg[dst[e]], 1);
}

__global__ void scan1_kernel() {
    __shared__ int wsum[8];
    int idx  = blockIdx.x * 256 + threadIdx.x;
    int lane = threadIdx.x & 31, wid = threadIdx.x >> 5;
    int v = (idx < NN) ? g_deg[idx] : 0;
    int x = v;
    #pragma unroll
    for (int o = 1; o < 32; o <<= 1) {
        int y = __shfl_up_sync(0xFFFFFFFFu, x, o);
        if (lane >= o) x += y;
    }
    if (lane == 31) wsum[wid] = x;
    __syncthreads();
    if (threadIdx.x == 0) {
        int csum = 0;
        #pragma unroll
        for (int w = 0; w < 8; w++) { int t = wsum[w]; wsum[w] = csum; csum += t; }
        g_bsum[blockIdx.x] = csum;
    }
    __syncthreads();
    if (idx < NN) g_rowptr[idx] = x - v + wsum[wid];
}

__global__ void scan2_kernel() {
    __shared__ int ws[16];
    int tid  = threadIdx.x;
    int lane = tid & 31, wid = tid >> 5;
    int v = (tid < 391) ? g_bsum[tid] : 0;
    int x = v;
    #pragma unroll
    for (int o = 1; o < 32; o <<= 1) {
        int y = __shfl_up_sync(0xFFFFFFFFu, x, o);
        if (lane >= o) x += y;
    }
    if (lane == 31) ws[wid] = x;
    __syncthreads();
    if (wid == 0) {
        int s = (lane < 16) ? ws[lane] : 0;
        #pragma unroll
        for (int o = 1; o < 16; o <<= 1) {
            int y = __shfl_up_sync(0xFFFFFFFFu, s, o);
            if (lane >= o) s += y;
        }
        if (lane < 16) ws[lane] = s;
    }
    __syncthreads();
    int excl = x - v + (wid ? ws[wid - 1] : 0);
    if (tid < 391) g_bsum[tid] = excl;
    if (tid == 390) g_bsum[391] = excl + v;
}

__global__ void scan3_kernel() {
    int idx = blockIdx.x * 256 + threadIdx.x;
    if (idx < NN) {
        int r = g_rowptr[idx] + g_bsum[blockIdx.x];
        g_rowptr[idx] = r;
        g_cursor[idx] = r;
        g_dis[idx]    = rsqrtf((float)(g_deg[idx] + 1));
    }
    if (idx == 0) g_rowptr[NN] = g_bsum[391];
}

__global__ void fill_kernel(const int* __restrict__ src, const int* __restrict__ dst) {
    int e = blockIdx.x * 256 + threadIdx.x;
    if (e < EE) {
        int d = dst[e];
        int p = atomicAdd(&g_cursor[d], 1);
        g_col[p] = src[e];
    }
}

// ---------------- GEMM1: g_t = fp16(x @ W1)  (bf16 hi/lo 3xMMA) ----------------
__global__ void __launch_bounds__(256, 2)
gemm_tc(const float* __restrict__ A, const unsigned char* __restrict__ wpack,
        const float* __restrict__ Wfull) {
    extern __shared__ char sm[];
    int tid  = threadIdx.x;
    int row0 = blockIdx.x * 128;
    constexpr int K = DIN_;

#if TC_OK
    uint32_t sb  = smem_u32(sm);
    int wid  = tid >> 5;
    int lane = tid & 31;
    constexpr int NC = K / 64;

    if (wid == 0) { tc_alloc(sb + GSM_HDR, 128); tc_relinq(); }
    if (tid == 0) mbar_init(sb + GSM_HDR + 8, 1);
    __syncthreads();
    uint32_t tmem;
    asm volatile("ld.shared.b32 %0, [%1];" : "=r"(tmem) : "r"(sb + GSM_HDR));
    uint32_t mb = sb + GSM_HDR + 8;

    auto load_chunk = [&](int c) {
        char* tile = sm;
        {
            int r = tid >> 1, h = tid & 1;
            int grow = row0 + r;
            const float* ap = A + (size_t)grow * K + c * 64 + h * 32;
            #pragma unroll
            for (int i = 0; i < 4; i++) {
                float v[8];
                if (grow < NN) {
                    float4 p0 = *(const float4*)(ap + i * 8);
                    float4 p1 = *(const float4*)(ap + i * 8 + 4);
                    v[0] = p0.x; v[1] = p0.y; v[2] = p0.z; v[3] = p0.w;
                    v[4] = p1.x; v[5] = p1.y; v[6] = p1.z; v[7] = p1.w;
                } else {
                    #pragma unroll
                    for (int j = 0; j < 8; j++) v[j] = 0.f;
                }
                uint32_t hi[4], lo[4];
                split8(v, hi, lo);
                uint32_t so = sw128((uint32_t)(r * 128 + h * 64 + i * 16));
                *(uint4*)(tile + so)         = make_uint4(hi[0], hi[1], hi[2], hi[3]);
                *(uint4*)(tile + 16384 + so) = make_uint4(lo[0], lo[1], lo[2], lo[3]);
            }
        }
        {
            const uint4* ws = (const uint4*)(wpack + (size_t)c * 32768);
            uint4* bd = (uint4*)(tile + 32768);
            #pragma unroll
            for (int i = 0; i < 8; i++) {
                int idx = tid + 256 * i;
                bd[idx] = __ldg(&ws[idx]);
            }
        }
    };

    load_chunk(0);
    fence_async();
    __syncthreads();

    uint64_t ah = smem_desc(sb);
    uint64_t al = smem_desc(sb + 16384);
    uint64_t bh = smem_desc(sb + 32768);
    uint64_t bl = smem_desc(sb + 49152);

    for (int c = 0; c < NC; c++) {
        if (wid == 0 && elect1()) {
            #pragma unroll
            for (int k = 0; k < 4; k++) {
                mma_f16k(tmem, ah + k * 2, bh + k * 2, IDESC_BF16, (c > 0) || (k > 0));
                mma_f16k(tmem, al + k * 2, bh + k * 2, IDESC_BF16, 1);
                mma_f16k(tmem, ah + k * 2, bl + k * 2, IDESC_BF16, 1);
            }
            tc_commit(mb);
        }
        if (c + 1 < NC) {
            mbar_wait(mb, (uint32_t)(c & 1));
            load_chunk(c + 1);
            fence_async();
            __syncthreads();
        }
    }
    mbar_wait(mb, (uint32_t)((NC - 1) & 1));
    tc_fence_after();

    // epilogue: fp16 output via smem (144B row stride)
    int wsub  = wid & 3;
    int chalf = (wid >> 2) * 32;
    int lr    = wsub * 32 + lane;
    #pragma unroll
    for (int p = 0; p < 2; p++) {
        uint32_t regs[32];
        ldtm_x32(regs, tmem + p * 64 + chalf);
        tc_wait_ld();
        uint32_t h[16];
        #pragma unroll
        for (int j = 0; j < 16; j++) {
            __half2 hh = __floats2half2_rn(__uint_as_float(regs[2 * j]),
                                           __uint_as_float(regs[2 * j + 1]));
            h[j] = *(uint32_t*)&hh;
        }
        #pragma unroll
        for (int j = 0; j < 4; j++)
            *(uint4*)(sm + lr * 144 + chalf * 2 + j * 16) =
                make_uint4(h[4 * j], h[4 * j + 1], h[4 * j + 2], h[4 * j + 3]);
        __syncthreads();
        #pragma unroll
        for (int i = 0; i < 4; i++) {
            int idx = tid + 256 * i;
            int r   = idx >> 3;
            int g   = idx & 7;
            int gr  = row0 + r;
            if (gr < NN)
                *(uint4*)&g_t[(size_t)gr * HH + p * 64 + g * 8] = *(uint4*)(sm + r * 144 + g * 16);
        }
        __syncthreads();
    }
    if (wid == 0) tc_dealloc(tmem, 128);

#else
    // fallback fp32 FFMA GEMM (fp16 output) reading Wfull (row-major fp32)
    float* As = (float*)sm;
    float* Bs = (float*)(sm + 8192);
    int tx = tid & 15, ty = tid >> 4;
    float acc[8][8];
    #pragma unroll
    for (int i = 0; i < 8; i++)
        #pragma unroll
        for (int j = 0; j < 8; j++) acc[i][j] = 0.f;
    for (int kk = 0; kk < K; kk += 16) {
        #pragma unroll
        for (int it = 0; it < 2; it++) {
            int idx = tid + 256 * it;
            int r  = idx >> 2;
            int k4 = idx & 3;
            int grow = row0 + r;
            float4 v = make_float4(0.f, 0.f, 0.f, 0.f);
            if (grow < NN) v = *(const float4*)&A[(size_t)grow * K + kk + k4 * 4];
            As[(k4 * 4 + 0) * 128 + r] = v.x;
            As[(k4 * 4 + 1) * 128 + r] = v.y;
            As[(k4 * 4 + 2) * 128 + r] = v.z;
            As[(k4 * 4 + 3) * 128 + r] = v.w;
        }
        #pragma unroll
        for (int it = 0; it < 2; it++) {
            int idx = tid + 256 * it;
            int kr = idx >> 5;
            int c4 = idx & 31;
            *(float4*)&Bs[kr * 128 + c4 * 4] = *(const float4*)&Wfull[(size_t)(kk + kr) * 128 + c4 * 4];
        }
        __syncthreads();
        #pragma unroll
        for (int k = 0; k < 16; k++) {
            float a[8], b[8];
            #pragma unroll
            for (int i = 0; i < 8; i++) a[i] = As[k * 128 + ty * 8 + i];
            #pragma unroll
            for (int j = 0; j < 8; j++) b[j] = Bs[k * 128 + tx * 8 + j];
            #pragma unroll
            for (int i = 0; i < 8; i++)
                #pragma unroll
                for (int j = 0; j < 8; j++) acc[i][j] = fmaf(a[i], b[j], acc[i][j]);
        }
        __syncthreads();
    }
    #pragma unroll
    for (int i = 0; i < 8; i++) {
        int row = row0 + ty * 8 + i;
        if (row < NN) {
            __half2 h0 = __floats2half2_rn(acc[i][0], acc[i][1]);
            __half2 h1 = __floats2half2_rn(acc[i][2], acc[i][3]);
            __half2 h2 = __floats2half2_rn(acc[i][4], acc[i][5]);
            __half2 h3 = __floats2half2_rn(acc[i][6], acc[i][7]);
            *(uint4*)&g_t[(size_t)row * HH + tx * 8] =
                make_uint4(*(uint32_t*)&h0, *(uint32_t*)&h1, *(uint32_t*)&h2, *(uint32_t*)&h3);
        }
    }
#endif
}

// ---------------- GEMM f16 (layers 2,3): g_t = fp16(dis * (relu(bn(agg)) @ W)) ----
__global__ void __launch_bounds__(256, 4)
gemm_f16(const unsigned char* __restrict__ wpack, const float* __restrict__ Wfull,
         const float* __restrict__ gamma, const float* __restrict__ beta,
         const float* __restrict__ bsum, const float* __restrict__ bsumsq) {
    extern __shared__ char sm[];
    const float* A = (const float*)g_agg;
    int tid  = threadIdx.x;
    int row0 = blockIdx.x * 128;

#if TC_OK
    uint32_t sb  = smem_u32(sm);
    int wid  = tid >> 5;
    int lane = tid & 31;
    float* bnsc = (float*)(sm + GSMF_BNSC);
    float* bnsh = (float*)(sm + GSMF_BNSH);

    if (tid == 0) mbar_init(sb + GSMF_HDR + 8, 1);
    if (tid < 128) {
        float mu  = bsum[tid] * (1.0f / (float)NN);
        float var = bsumsq[tid] * (1.0f / (float)NN) - mu * mu;
        float sc  = gamma[tid] * rsqrtf(var + EPSF);
        bnsc[tid] = sc;
        bnsh[tid] = beta[tid] - mu * sc;
    }
    __syncthreads();

    auto load_chunk = [&](int c) {
        {
            int r = tid >> 1, h = tid & 1;
            int grow = row0 + r;
            const float* ap = A + (size_t)grow * HH + c * 64 + h * 32;
            #pragma unroll
            for (int i = 0; i < 4; i++) {
                float v[8];
                if (grow < NN) {
                    float4 p0 = *(const float4*)(ap + i * 8);
                    float4 p1 = *(const float4*)(ap + i * 8 + 4);
                    v[0] = p0.x; v[1] = p0.y; v[2] = p0.z; v[3] = p0.w;
                    v[4] = p1.x; v[5] = p1.y; v[6] = p1.z; v[7] = p1.w;
                } else {
                    #pragma unroll
                    for (int j = 0; j < 8; j++) v[j] = 0.f;
                }
                int col = c * 64 + h * 32 + i * 8;
                #pragma unroll
                for (int j = 0; j < 8; j++)
                    v[j] = fmaxf(0.f, fmaf(v[j], bnsc[col + j], bnsh[col + j]));
                __half2 h0 = __floats2half2_rn(v[0], v[1]);
                __half2 h1 = __floats2half2_rn(v[2], v[3]);
                __half2 h2 = __floats2half2_rn(v[4], v[5]);
                __half2 h3 = __floats2half2_rn(v[6], v[7]);
                uint32_t so = sw128((uint32_t)(r * 128 + h * 64 + i * 16));
                *(uint4*)(sm + so) = make_uint4(*(uint32_t*)&h0, *(uint32_t*)&h1,
                                                *(uint32_t*)&h2, *(uint32_t*)&h3);
            }
        }
        {
            const uint4* ws = (const uint4*)(wpack + (size_t)c * 16384);
            uint4* bd = (uint4*)(sm + 16384);
            #pragma unroll
            for (int i = 0; i < 4; i++) {
                int idx = tid + 256 * i;
                bd[idx] = __ldg(&ws[idx]);
            }
        }
    };

    load_chunk(0);
    fence_async();
    __syncthreads();
    if (wid == 0) { tc_alloc(sb + GSMF_HDR, 128); tc_relinq(); }
    __syncthreads();
    uint32_t tmem;
    asm volatile("ld.shared.b32 %0, [%1];" : "=r"(tmem) : "r"(sb + GSMF_HDR));
    uint32_t mb = sb + GSMF_HDR + 8;

    uint64_t ad = smem_desc(sb);
    uint64_t bd = smem_desc(sb + 16384);

    #pragma unroll
    for (int c = 0; c < 2; c++) {
        if (wid == 0 && elect1()) {
            #pragma unroll
            for (int k = 0; k < 4; k++)
                mma_f16k(tmem, ad + k * 2, bd + k * 2, IDESC_F16, (c > 0) || (k > 0));
            tc_commit(mb);
        }
        if (c == 0) {
            mbar_wait(mb, 0u);
            load_chunk(1);
            fence_async();
            __syncthreads();
        }
    }
    mbar_wait(mb, 1u);
    tc_fence_after();

    // epilogue: dis-scale, fp16 to smem (144B rows), coalesced STG
    int wsub  = wid & 3;
    int chalf = (wid >> 2) * 32;
    int lr    = wsub * 32 + lane;
    int growE = row0 + lr;
    float dv  = (growE < NN) ? g_dis[growE] : 0.f;
    #pragma unroll
    for (int p = 0; p < 2; p++) {
        uint32_t regs[32];
        ldtm_x32(regs, tmem + p * 64 + chalf);
        tc_wait_ld();
        uint32_t h[16];
        #pragma unroll
        for (int j = 0; j < 16; j++) {
            __half2 hh = __floats2half2_rn(dv * __uint_as_float(regs[2 * j]),
                                           dv * __uint_as_float(regs[2 * j + 1]));
            h[j] = *(uint32_t*)&hh;
        }
        #pragma unroll
        for (int j = 0; j < 4; j++)
            *(uint4*)(sm + lr * 144 + chalf * 2 + j * 16) =
                make_uint4(h[4 * j], h[4 * j + 1], h[4 * j + 2], h[4 * j + 3]);
        __syncthreads();
        #pragma unroll
        for (int i = 0; i < 4; i++) {
            int idx = tid + 256 * i;
            int r   = idx >> 3;
            int g   = idx & 7;
            int gr  = row0 + r;
            if (gr < NN)
                *(uint4*)&g_t[(size_t)gr * HH + p * 64 + g * 8] = *(uint4*)(sm + r * 144 + g * 16);
        }
        __syncthreads();
    }
    if (wid == 0) tc_dealloc(tmem, 128);

#else
    // fallback fp32 FFMA GEMM with BN (fp16 output) reading Wfull (row-major fp32)
    float* As = (float*)sm;
    float* Bs = (float*)(sm + 8192);
    float* bnsc = (float*)(sm + GSMF_BNSC);
    float* bnsh = (float*)(sm + GSMF_BNSH);
    if (tid < 128) {
        float mu  = bsum[tid] * (1.0f / (float)NN);
        float var = bsumsq[tid] * (1.0f / (float)NN) - mu * mu;
        float sc  = gamma[tid] * rsqrtf(var + EPSF);
        bnsc[tid] = sc;
        bnsh[tid] = beta[tid] - mu * sc;
    }
    __syncthreads();
    int tx = tid & 15, ty = tid >> 4;
    float acc[8][8];
    #pragma unroll
    for (int i = 0; i < 8; i++)
        #pragma unroll
        for (int j = 0; j < 8; j++) acc[i][j] = 0.f;
    for (int kk = 0; kk < HH; kk += 16) {
        #pragma unroll
        for (int it = 0; it < 2; it++) {
            int idx = tid + 256 * it;
            int r  = idx >> 2;
            int k4 = idx & 3;
            int grow = row0 + r;
            float4 v = make_float4(0.f, 0.f, 0.f, 0.f);
            if (grow < NN) v = *(const float4*)&A[(size_t)grow * HH + kk + k4 * 4];
            int c = kk + k4 * 4;
            v.x = fmaxf(0.f, fmaf(v.x, bnsc[c + 0], bnsh[c + 0]));
            v.y = fmaxf(0.f, fmaf(v.y, bnsc[c + 1], bnsh[c + 1]));
            v.z = fmaxf(0.f, fmaf(v.z, bnsc[c + 2], bnsh[c + 2]));
            v.w = fmaxf(0.f, fmaf(v.w, bnsc[c + 3], bnsh[c + 3]));
            As[(k4 * 4 + 0) * 128 + r] = v.x;
            As[(k4 * 4 + 1) * 128 + r] = v.y;
            As[(k4 * 4 + 2) * 128 + r] = v.z;
            As[(k4 * 4 + 3) * 128 + r] = v.w;
        }
        #pragma unroll
        for (int it = 0; it < 2; it++) {
            int idx = tid + 256 * it;
            int kr = idx >> 5;
            int c4 = idx & 31;
            *(float4*)&Bs[kr * 128 + c4 * 4] = *(const float4*)&Wfull[(size_t)(kk + kr) * 128 + c4 * 4];
        }
        __syncthreads();
        #pragma unroll
        for (int k = 0; k < 16; k++) {
            float a[8], b[8];
            #pragma unroll
            for (int i = 0; i < 8; i++) a[i] = As[k * 128 + ty * 8 + i];
            #pragma unroll
            for (int j = 0; j < 8; j++) b[j] = Bs[k * 128 + tx * 8 + j];
            #pragma unroll
            for (int i = 0; i < 8; i++)
                #pragma unroll
                for (int j = 0; j < 8; j++) acc[i][j] = fmaf(a[i], b[j], acc[i][j]);
        }
        __syncthreads();
    }
    #pragma unroll
    for (int i = 0; i < 8; i++) {
        int row = row0 + ty * 8 + i;
        if (row < NN) {
            float dv = g_dis[row];
            __half2 h0 = __floats2half2_rn(dv * acc[i][0], dv * acc[i][1]);
            __half2 h1 = __floats2half2_rn(dv * acc[i][2], dv * acc[i][3]);
            __half2 h2 = __floats2half2_rn(dv * acc[i][4], dv * acc[i][5]);
            __half2 h3 = __floats2half2_rn(dv * acc[i][6], dv * acc[i][7]);
            *(uint4*)&g_t[(size_t)row * HH + tx * 8] =
                make_uint4(*(uint32_t*)&h0, *(uint32_t*)&h1, *(uint32_t*)&h2, *(uint32_t*)&h3);
        }
    }
#endif
}

// ---------------- aggregation + fused BN stats (R11-exact: half-warp/node, 2-deep) ----
#define AGG_BLOCKS 1184
template <bool EDGE_DIS>
__global__ void __launch_bounds__(256) agg_kernel(const float* __restrict__ bias,
                                                  float* __restrict__ bsum,
                                                  float* __restrict__ bsumsq) {
    __shared__ float spart[16][128];
    int hw = threadIdx.x >> 4;       // half-warp id 0..15
    int hl = threadIdx.x & 15;       // lane within half-warp
    int node0 = blockIdx.x * 16 + hw;
    const int stride = AGG_BLOCKS * 16;
    const uint4* t4 = (const uint4*)g_t;     // 16 uint4 per 128-half row
    float4 bb0 = ((const float4*)bias)[hl * 2];
    float4 bb1 = ((const float4*)bias)[hl * 2 + 1];

    float ps[8], pq[8];
    #pragma unroll
    for (int j = 0; j < 8; j++) { ps[j] = 0.f; pq[j] = 0.f; }

    for (int v = node0; v < NN; v += stride) {
        int beg = g_rowptr[v], end = g_rowptr[v + 1];
        float a0[8], a1[8];
        #pragma unroll
        for (int j = 0; j < 8; j++) { a0[j] = 0.f; a1[j] = 0.f; }
        int e  = beg;
        int sA = (e     < end) ? __ldg(&g_col[e])     : 0;
        int sB = (e + 1 < end) ? __ldg(&g_col[e + 1]) : 0;
        while (e + 2 <= end) {
            int sa = sA, sb = sB;
            sA = (e + 2 < end) ? __ldg(&g_col[e + 2]) : 0;
            sB = (e + 3 < end) ? __ldg(&g_col[e + 3]) : 0;
            uint4 ua = __ldg(&t4[(size_t)sa * 16 + hl]);
            uint4 ub = __ldg(&t4[(size_t)sb * 16 + hl]);
            float4 ta0 = h4_to_f4(make_uint2(ua.x, ua.y));
            float4 ta1 = h4_to_f4(make_uint2(ua.z, ua.w));
            float4 tb0 = h4_to_f4(make_uint2(ub.x, ub.y));
            float4 tb1 = h4_to_f4(make_uint2(ub.z, ub.w));
            if (EDGE_DIS) {
                float wa = __ldg(&g_dis[sa]);
                float wb = __ldg(&g_dis[sb]);
                a0[0] = fmaf(wa, ta0.x, a0[0]); a0[1] = fmaf(wa, ta0.y, a0[1]);
                a0[2] = fmaf(wa, ta0.z, a0[2]); a0[3] = fmaf(wa, ta0.w, a0[3]);
                a0[4] = fmaf(wa, ta1.x, a0[4]); a0[5] = fmaf(wa, ta1.y, a0[5]);
                a0[6] = fmaf(wa, ta1.z, a0[6]); a0[7] = fmaf(wa, ta1.w, a0[7]);
                a1[0] = fmaf(wb, tb0.x, a1[0]); a1[1] = fmaf(wb, tb0.y, a1[1]);
                a1[2] = fmaf(wb, tb0.z, a1[2]); a1[3] = fmaf(wb, tb0.w, a1[3]);
                a1[4] = fmaf(wb, tb1.x, a1[4]); a1[5] = fmaf(wb, tb1.y, a1[5]);
                a1[6] = fmaf(wb, tb1.z, a1[6]); a1[7] = fmaf(wb, tb1.w, a1[7]);
            } else {
                a0[0] += ta0.x; a0[1] += ta0.y; a0[2] += ta0.z; a0[3] += ta0.w;
                a0[4] += ta1.x; a0[5] += ta1.y; a0[6] += ta1.z; a0[7] += ta1.w;
                a1[0] += tb0.x; a1[1] += tb0.y; a1[2] += tb0.z; a1[3] += tb0.w;
                a1[4] += tb1.x; a1[5] += tb1.y; a1[6] += tb1.z; a1[7] += tb1.w;
            }
            e += 2;
        }
        if (e < end) {
            uint4 ua = __ldg(&t4[(size_t)sA * 16 + hl]);
            float4 ta0 = h4_to_f4(make_uint2(ua.x, ua.y));
            float4 ta1 = h4_to_f4(make_uint2(ua.z, ua.w));
            if (EDGE_DIS) {
                float wa = __ldg(&g_dis[sA]);
                a0[0] = fmaf(wa, ta0.x, a0[0]); a0[1] = fmaf(wa, ta0.y, a0[1]);
                a0[2] = fmaf(wa, ta0.z, a0[2]); a0[3] = fmaf(wa, ta0.w, a0[3]);
                a0[4] = fmaf(wa, ta1.x, a0[4]); a0[5] = fmaf(wa, ta1.y, a0[5]);
                a0[6] = fmaf(wa, ta1.z, a0[6]); a0[7] = fmaf(wa, ta1.w, a0[7]);
            } else {
                a0[0] += ta0.x; a0[1] += ta0.y; a0[2] += ta0.z; a0[3] += ta0.w;
                a0[4] += ta1.x; a0[5] += ta1.y; a0[6] += ta1.z; a0[7] += ta1.w;
            }
        }
        float dv = g_dis[v];
        uint4 us = t4[(size_t)v * 16 + hl];
        float4 sv0 = h4_to_f4(make_uint2(us.x, us.y));
        float4 sv1 = h4_to_f4(make_uint2(us.z, us.w));
        float svv[8] = { sv0.x, sv0.y, sv0.z, sv0.w, sv1.x, sv1.y, sv1.z, sv1.w };
        float bbv[8] = { bb0.x, bb0.y, bb0.z, bb0.w, bb1.x, bb1.y, bb1.z, bb1.w };
        float o[8];
        #pragma unroll
        for (int j = 0; j < 8; j++) {
            if (EDGE_DIS)
                o[j] = fmaf(dv, fmaf(dv, svv[j], a0[j] + a1[j]), bbv[j]);
            else
                o[j] = fmaf(dv, a0[j] + a1[j] + svv[j], bbv[j]);
        }
        float* op = &g_agg[(size_t)v * HH + hl * 8];
        *(float4*)(op)     = make_float4(o[0], o[1], o[2], o[3]);
        *(float4*)(op + 4) = make_float4(o[4], o[5], o[6], o[7]);
        #pragma unroll
        for (int j = 0; j < 8; j++) {
            ps[j] += o[j];
            pq[j]  = fmaf(o[j], o[j], pq[j]);
        }
    }

    // block reduce: 16 half-warps x 128 cols
    *(float4*)&spart[hw][hl * 8]     = make_float4(ps[0], ps[1], ps[2], ps[3]);
    *(float4*)&spart[hw][hl * 8 + 4] = make_float4(ps[4], ps[5], ps[6], ps[7]);
    __syncthreads();
    if (threadIdx.x < 128) {
        float s = 0.f;
        #pragma unroll
        for (int w = 0; w < 16; w++) s += spart[w][threadIdx.x];
        atomicAdd(&bsum[threadIdx.x], s);
    }
    __syncthreads();
    *(float4*)&spart[hw][hl * 8]     = make_float4(pq[0], pq[1], pq[2], pq[3]);
    *(float4*)&spart[hw][hl * 8 + 4] = make_float4(pq[4], pq[5], pq[6], pq[7]);
    __syncthreads();
    if (threadIdx.x < 128) {
        float s = 0.f;
        #pragma unroll
        for (int w = 0; w < 16; w++) s += spart[w][threadIdx.x];
        atomicAdd(&bsumsq[threadIdx.x], s);
    }
}

// ---------------- final projection (BN3 inline, grid-stride, coeffs hoisted) ----------
#define FIN_BLOCKS 1184
__global__ void __launch_bounds__(256) final_kernel(const float* __restrict__ Wf,
                                                    const float* __restrict__ bf,
                                                    const float* __restrict__ gamma,
                                                    const float* __restrict__ beta,
                                                    float* __restrict__ out) {
    int wid  = threadIdx.x >> 5;
    int lane = threadIdx.x & 31;
    float4 S  = ((const float4*)g_sums[2])[lane];
    float4 Q  = ((const float4*)g_sumsqs[2])[lane];
    float4 gm = ((const float4*)gamma)[lane];
    float4 be = ((const float4*)beta)[lane];
    const float inv = 1.0f / (float)NN;
    float mux = S.x * inv, muy = S.y * inv, muz = S.z * inv, muw = S.w * inv;
    float scx = gm.x * rsqrtf(Q.x * inv - mux * mux + EPSF);
    float scy = gm.y * rsqrtf(Q.y * inv - muy * muy + EPSF);
    float scz = gm.z * rsqrtf(Q.z * inv - muz * muz + EPSF);
    float scw = gm.w * rsqrtf(Q.w * inv - muw * muw + EPSF);
    float shx = be.x - mux * scx, shy = be.y - muy * scy;
    float shz = be.z - muz * scz, shw = be.w - muw * scw;
    float4 w  = ((const float4*)Wf)[lane];
    float bf0 = bf[0];

    for (int v = blockIdx.x * 8 + wid; v < NN; v += FIN_BLOCKS * 8) {
        float4 h = ((const float4*)g_agg)[(size_t)v * 32 + lane];
        float r = fmaxf(0.f, fmaf(h.x, scx, shx)) * w.x
                + fmaxf(0.f, fmaf(h.y, scy, shy)) * w.y
                + fmaxf(0.f, fmaf(h.z, scz, shz)) * w.z
                + fmaxf(0.f, fmaf(h.w, scw, shw)) * w.w;
        #pragma unroll
        for (int o = 16; o; o >>= 1) r += __shfl_down_sync(0xFFFFFFFFu, r, o);
        if (lane == 0) out[v] = r + bf0;
    }
}

// ---------------- launch ----------------
extern "C" void kernel_launch(void* const* d_in, const int* in_sizes, int n_in,
                              void* d_out, int out_size) {
    const float* x   = (const float*)d_in[0];
    const int*   src = (const int*)d_in[1];
    const int*   dst = (const int*)d_in[2];
    const float* W1  = (const float*)d_in[3];
    const float* b1  = (const float*)d_in[4];
    const float* g1  = (const float*)d_in[5];
    const float* be1 = (const float*)d_in[6];
    const float* W2  = (const float*)d_in[7];
    const float* b2  = (const float*)d_in[8];
    const float* g2  = (const float*)d_in[9];
    const float* be2 = (const float*)d_in[10];
    const float* W3  = (const float*)d_in[11];
    const float* b3  = (const float*)d_in[12];
    const float* g3  = (const float*)d_in[13];
    const float* be3 = (const float*)d_in[14];
    const float* Wf  = (const float*)d_in[15];
    const float* bf  = (const float*)d_in[16];
    float* out = (float*)d_out;

    cudaFuncSetAttribute(gemm_tc,  cudaFuncAttributeMaxDynamicSharedMemorySize, GSM_TOTAL);
    cudaFuncSetAttribute(gemm_f16, cudaFuncAttributeMaxDynamicSharedMemorySize, GSMF_TOTAL);

    unsigned char* wp;
    cudaGetSymbolAddress((void**)&wp, g_wpack);
    float *sums, *sumsqs;
    cudaGetSymbolAddress((void**)&sums,   g_sums);
    cudaGetSymbolAddress((void**)&sumsqs, g_sumsqs);

    const int EB = (EE + 255) / 256;
    const int NB = (NN + 255) / 256;               // 391
    const int GB = (NN + 127) / 128;               // 782

    static cudaStream_t s2 = nullptr;
    static cudaEvent_t evFork = nullptr, evJoin = nullptr;
    static int stream_ok = -1;
    if (stream_ok < 0) {
        stream_ok = (cudaStreamCreateWithFlags(&s2, cudaStreamNonBlocking) == cudaSuccess &&
                     cudaEventCreateWithFlags(&evFork, cudaEventDisableTiming) == cudaSuccess &&
                     cudaEventCreateWithFlags(&evJoin, cudaEventDisableTiming) == cudaSuccess) ? 1 : 0;
    }

    if (stream_ok == 1) {
        cudaEventRecord(evFork, 0);
        cudaStreamWaitEvent(s2, evFork, 0);
        zero_deg_kernel<<<NB, 256, 0, s2>>>();
        count_kernel<<<EB, 256, 0, s2>>>(dst);
        scan1_kernel<<<NB, 256, 0, s2>>>();
        scan2_kernel<<<1, 512, 0, s2>>>();
        scan3_kernel<<<NB, 256, 0, s2>>>();
        fill_kernel<<<EB, 256, 0, s2>>>(src, dst);
        cudaEventRecord(evJoin, s2);

        prep_w<<<8, 256>>>(W1, W2, W3);
        gemm_tc<<<GB, 256, GSM_TOTAL>>>(x, wp, W1);
        cudaStreamWaitEvent(0, evJoin, 0);
    } else {
        zero_deg_kernel<<<NB, 256>>>();
        count_kernel<<<EB, 256>>>(dst);
        scan1_kernel<<<NB, 256>>>();
        scan2_kernel<<<1, 512>>>();
        scan3_kernel<<<NB, 256>>>();
        fill_kernel<<<EB, 256>>>(src, dst);
        prep_w<<<8, 256>>>(W1, W2, W3);
        gemm_tc<<<GB, 256, GSM_TOTAL>>>(x, wp, W1);
    }

    // layer 1: t unscaled -> per-edge dis agg
    agg_kernel<true><<<AGG_BLOCKS, 256>>>(b1, sums + 0 * HH, sumsqs + 0 * HH);

    // layer 2: fp16 single-MMA GEMM (BN from sums[0]); epilogue pre-scales by dis
    gemm_f16<<<GB, 256, GSMF_TOTAL>>>(wp + 131072, W2, g1, be1, sums + 0 * HH, sumsqs + 0 * HH);
    agg_kernel<false><<<AGG_BLOCKS, 256>>>(b2, sums + 1 * HH, sumsqs + 1 * HH);

    // layer 3
    gemm_f16<<<GB, 256, GSMF_TOTAL>>>(wp + 163840, W3, g2, be2, sums + 1 * HH, sumsqs + 1 * HH);
    agg_kernel<false><<<AGG_BLOCKS, 256>>>(b3, sums + 2 * HH, sumsqs + 2 * HH);

    // final projection (BN3 inline, grid-stride)
    final_kernel<<<FIN_BLOCKS, 256>>>(Wf, bf, g3, be3, out);
}